// round 9
// baseline (speedup 1.0000x reference)
#include <cuda_runtime.h>

#define EB     96
#define NTH    256
#define H_STR  101
#define F_STR  73
#define Y_STR  26
#define T_STR  41
#define WSH_PAD 10112
#define DPI    3.14159265358979323846

// ---------------- device globals (scratch, no allocation) ----------------
__device__ float g_CG[1225];
__device__ float g_K[25];
__device__ float g_norm[3];

// 19 tensor-product instances: (lo, li, l) with kk = index of l within the pair
__constant__ int c_lo[19]   = {0,0,0,1,1,1,1,1,1,1,2,2,2,2,2,2,2,2,2};
__constant__ int c_li[19]   = {0,1,2,0,1,1,1,2,2,2,0,1,1,1,2,2,2,2,2};
__constant__ int c_l [19]   = {0,1,2,1,0,1,2,1,2,3,2,1,2,3,0,1,2,3,4};
__constant__ int c_kk[19]   = {0,0,0,0,0,1,2,0,1,2,0,0,1,2,0,1,2,3,4};
__constant__ int c_roff[19] = {0,64,128,192,256,256,256,448,448,448,640,704,704,704,896,896,896,896,896};
__constant__ int c_foff[19] = {0,8,32,0,8,8,8,32,32,32,0,8,8,8,32,32,32,32,32};
__constant__ int c_cgoff[19]= {0,1,10,35,44,53,80,125,170,245,350,375,420,495,600,625,700,825,1000};
__constant__ int c_nl[19]   = {1,1,1,1,3,3,3,3,3,3,1,3,3,3,5,5,5,5,5};

// ---------------- packed f32x2 helpers (Blackwell FFMA2) ----------------
union F2U { unsigned long long u; float2 f; };

__device__ __forceinline__ unsigned long long pack2(float a){
    unsigned long long r;
    asm("mov.b64 %0, {%1, %1};" : "=l"(r) : "r"(__float_as_uint(a)));
    return r;
}
__device__ __forceinline__ void ffma2(unsigned long long& d,
                                      unsigned long long a, unsigned long long b){
    asm("fma.rn.f32x2 %0, %1, %2, %0;" : "+l"(d) : "l"(a), "l"(b));
}

// ---------------- CG init helpers (double precision, tiny one-shot kernel) ----------------
__device__ double dfact(int n){ double r=1.0; for(int i=2;i<=n;i++) r*=(double)i; return r; }

__device__ double w3j(int j1,int j2,int j3,int m1,int m2,int m3){
    if (m1+m2+m3 != 0) return 0.0;
    if (j3 < abs(j1-j2) || j3 > j1+j2) return 0.0;
    if (abs(m1)>j1 || abs(m2)>j2 || abs(m3)>j3) return 0.0;
    double pre = sqrt( dfact(j1+j2-j3)*dfact(j1-j2+j3)*dfact(-j1+j2+j3)/dfact(j1+j2+j3+1)
                     * dfact(j1+m1)*dfact(j1-m1)*dfact(j2+m2)*dfact(j2-m2)
                     * dfact(j3+m3)*dfact(j3-m3) );
    int kmin = max(0, max(j2-j3-m1, j1-j3+m2));
    int kmax = min(j1+j2-j3, min(j1-m1, j2+m2));
    double s = 0.0;
    for (int k=kmin;k<=kmax;k++){
        double den = dfact(k)*dfact(j1+j2-j3-k)*dfact(j1-m1-k)*dfact(j2+m2-k)
                   * dfact(j3-j2+m1+k)*dfact(j3-j1-m2+k);
        s += ((k&1)?-1.0:1.0)/den;
    }
    int ex = j1-j2-m3;
    double sgn = (ex & 1) ? -1.0 : 1.0;
    return sgn*pre*s;
}

// complex->real SH change-of-basis: row a (0..2l), complex col index m (-l..l)
__device__ void u_c2r(int l, int a, int m, double& re, double& im){
    re = 0.0; im = 0.0;
    const double is2 = 0.70710678118654752440;
    if (a == l){ if (m == 0) re = 1.0; return; }
    if (a > l){
        int mm = a - l;
        if      (m ==  mm) re = ((mm&1)?-1.0:1.0)*is2;
        else if (m == -mm) re = is2;
    } else {
        int mm = l - a;
        if      (m == -mm) im = is2;
        else if (m ==  mm) im = -((mm&1)?-1.0:1.0)*is2;
    }
}

__global__ void cg_init_kernel(){
    int idx = blockIdx.x*blockDim.x + threadIdx.x;
    int nth = gridDim.x*blockDim.x;

    if (idx < 25){  // SH normalization (sqrt(2) folded in for m != 0)
        int l = 0; while ((l+1)*(l+1) <= idx) l++;
        int m = idx - l*l - l;
        int am = m < 0 ? -m : m;
        double K = sqrt((2.0*l+1.0)/(4.0*DPI) * dfact(l-am)/dfact(l+am));
        if (m != 0) K *= sqrt(2.0);
        g_K[idx] = (float)K;
    }
    if (idx >= 25 && idx < 28){
        int lo = idx - 25;
        int nse = (lo==0)?24:(lo==1?56:72);
        g_norm[lo] = (float)(sqrt(4.0*DPI)*sqrt(2.0*lo+1.0)/sqrt((double)nse));
    }

    for (int e = idx; e < 1225; e += nth){
        int inst = 0;
        for (int i2=1;i2<19;i2++) if (e >= c_cgoff[i2]) inst = i2;
        int lo = c_lo[inst], li = c_li[inst], l3 = c_l[inst];
        int Q2 = 2*li+1, Rd = 2*l3+1;
        int off = e - c_cgoff[inst];
        int a = off/(Q2*Rd);
        int rem = off - a*Q2*Rd;
        int b = rem/Rd;
        int c = rem - b*Rd;
        double tre = 0.0, tim = 0.0;
        for (int m1=-lo;m1<=lo;m1++){
            double u1r,u1i; u_c2r(lo,a,m1,u1r,u1i);
            if (u1r==0.0 && u1i==0.0) continue;
            for (int m2=-li;m2<=li;m2++){
                double u2r,u2i; u_c2r(li,b,m2,u2r,u2i);
                if (u2r==0.0 && u2i==0.0) continue;
                int m3 = -(m1+m2);
                if (m3 < -l3 || m3 > l3) continue;
                double u3r,u3i; u_c2r(l3,c,m3,u3r,u3i);
                if (u3r==0.0 && u3i==0.0) continue;
                double w = w3j(lo,li,l3,m1,m2,m3);
                if (w == 0.0) continue;
                double p12r = u1r*u2r - u1i*u2i;
                double p12i = u1r*u2i + u1i*u2r;
                double pr = p12r*u3r - p12i*u3i;
                double pi = p12r*u3i + p12i*u3r;
                tre += pr*w; tim += pi*w;
            }
        }
        g_CG[e] = (float)(tre + tim);
    }
}

__global__ void zero_kernel(float* o, int n){
    int i = blockIdx.x*blockDim.x + threadIdx.x;
    if (i < n) o[i] = 0.f;
}

// ---------------- MLP layer with f32x2: dst[e][o] = silu(sum_k src[e][k]*Wsh[k][o]) ----
// Column partition: thread group ocol handles column pairs {ocol*2 + 16*j, +1}, j=0..6
// (all pairs even-aligned -> LDS.64 on W; covers cols 0..111, writes guarded to <100;
//  pad region of Wsh is zeroed so over-read lanes never see garbage).
__device__ __forceinline__ void mlp_layer(const float* __restrict__ src, float* __restrict__ dst,
                                          const float* __restrict__ Wsh, int lane, int ocol, int K){
    unsigned long long acc[3][7];
    #pragma unroll
    for (int i=0;i<3;i++)
        #pragma unroll
        for (int j=0;j<7;j++) acc[i][j] = 0ull;
    const int cb = ocol*2;
    for (int k=0;k<K;k++){
        unsigned long long hh0 = pack2(src[ lane      *H_STR + k]);
        unsigned long long hh1 = pack2(src[(lane+32)  *H_STR + k]);
        unsigned long long hh2 = pack2(src[(lane+64)  *H_STR + k]);
        #pragma unroll
        for (int j=0;j<7;j++){
            unsigned long long w = *(const unsigned long long*)&Wsh[k*100 + cb + 16*j];
            ffma2(acc[0][j], hh0, w);
            ffma2(acc[1][j], hh1, w);
            ffma2(acc[2][j], hh2, w);
        }
    }
    #pragma unroll
    for (int i=0;i<3;i++)
        #pragma unroll
        for (int j=0;j<7;j++){
            int c = cb + 16*j;
            F2U cv; cv.u = acc[i][j];
            if (c < 100){
                float v = cv.f.x;
                dst[(lane + 32*i)*H_STR + c] = v / (1.f + __expf(-v));
            }
            if (c + 1 < 100){
                float v = cv.f.y;
                dst[(lane + 32*i)*H_STR + c + 1] = v / (1.f + __expf(-v));
            }
        }
}

// prefetch next W3 tile into registers (25 per thread); layout: flat i = tid + j*256,
// k = i>>6, c = i&63, value = W3[k*1216 + roff + c*nl + kk] / sqrt(100)
__device__ __forceinline__ void w3_prefetch(const float* __restrict__ W3, int inst,
                                            int tid, float* wreg){
    const int roff = c_roff[inst], nl = c_nl[inst], kk = c_kk[inst];
    #pragma unroll
    for (int j=0;j<25;j++){
        int i = tid + j*NTH;
        int k = i >> 6, c = i & 63;
        wreg[j] = W3[k*1216 + roff + c*nl + kk] * 0.1f;
    }
}

// ---------------- main fused kernel ----------------
__global__ void __launch_bounds__(NTH, 1)
tfn_main(const int* __restrict__ ei, const float* __restrict__ x,
         const float* __restrict__ dist, const float* __restrict__ rvec,
         const float* __restrict__ W0, const float* __restrict__ W1,
         const float* __restrict__ W2, const float* __restrict__ W3,
         float* __restrict__ out, int E)
{
    extern __shared__ float sm[];
    float* A   = sm;                    // [96][101]  h1 / h3
    float* B   = A   + EB*H_STR;        // [96][101]  h0 / h2
    float* Wsh = B   + EB*H_STR;        // WSH_PAD floats: W0/W1/W2 staged; then W3 tile [100][64]
    float* F   = Wsh + WSH_PAD;         // [96][73]
    float* Ysh = F   + EB*F_STR;        // [96][26]
    float* T   = Ysh + EB*Y_STR;        // [96][41]
    float* CGs = T   + EB*T_STR;        // 1225 (padded 1232)
    int*  DST  = (int*)(CGs + 1232);    // [96]

    const int tid  = threadIdx.x;
    const int lane = tid & 31;
    const int ocol = tid >> 5;          // 0..7
    const int base = blockIdx.x * EB;
    const int e_act = min(EB, E - base);

    // per-thread message accumulators: 3 edges x 9 cols (rep0:1, rep1:3, rep2:5) for u=ocol
    float msg_acc[3][9];
    #pragma unroll
    for (int i=0;i<3;i++)
        #pragma unroll
        for (int s=0;s<9;s++) msg_acc[i][s] = 0.f;

    // ---- stage S0: W0 (+zero pad), CG, basis -> B, spherical harmonics, F gather ----
    for (int i = tid; i < 1000; i += NTH) Wsh[i] = W0[i] * 0.31622776601683794f; // /sqrt(10)
    for (int i = 10000 + tid; i < WSH_PAD; i += NTH) Wsh[i] = 0.f;               // pad (read-only lanes)
    for (int i = tid; i < 1225; i += NTH) CGs[i] = g_CG[i];

    if (tid < EB){
        int e = tid;
        bool act = (e < e_act);
        DST[e] = act ? ei[E + base + e] : 0;

        // gaussian basis
        float d = act ? dist[base + e] : 0.f;
        #pragma unroll
        for (int k=0;k<10;k++){
            float c = 0.7f + (2.5f/9.f)*(float)k;
            float t = (d - c) * 4.5f;                       // 1/sigma = 9/(0.8*2.5)
            B[e*H_STR + k] = act ? __expf(-t*t) * (1.f/1.423085244900308f) : 0.f;
        }

        // spherical harmonics (lmax=4), matching reference recurrences
        float vx=0.f, vy=0.f, vz=0.f;
        if (act){ vx = rvec[(base+e)*3]; vy = rvec[(base+e)*3+1]; vz = rvec[(base+e)*3+2]; }
        float r   = sqrtf(vx*vx + vy*vy + vz*vz);
        float inv = 1.f / fmaxf(r, 1e-9f);
        float X = vx*inv, Yc = vy*inv, Z = vz*inv;
        float Am[5], Bm[5];
        Am[0] = 1.f; Bm[0] = 0.f;
        #pragma unroll
        for (int m=1;m<=4;m++){
            Am[m] = X*Am[m-1] - Yc*Bm[m-1];
            Bm[m] = X*Bm[m-1] + Yc*Am[m-1];
        }
        float P[5][5];
        P[0][0] = 1.f;
        #pragma unroll
        for (int m=0;m<=4;m++){
            if (m > 0) P[m][m] = -(2.f*m - 1.f)*P[m-1][m-1];
            if (m < 4) P[m+1][m] = (2.f*m + 1.f)*Z*P[m][m];
            #pragma unroll
            for (int l=m+2;l<=4;l++)
                P[l][m] = ((2.f*l - 1.f)*Z*P[l-1][m] - (l + m - 1.f)*P[l-2][m]) / (float)(l - m);
        }
        if (act){
            int idx = 0;
            #pragma unroll
            for (int l=0;l<=4;l++){
                #pragma unroll
                for (int m=-l;m<=l;m++,idx++){
                    int am = (m < 0) ? -m : m;
                    float K = g_K[idx];
                    float val = (m == 0) ? K*P[l][0]
                              : (m > 0)  ? K*P[l][m]*Am[m]
                                         : K*P[l][am]*Bm[am];
                    Ysh[e*Y_STR + idx] = val;
                }
            }
        } else {
            for (int idx=0; idx<25; idx++) Ysh[e*Y_STR + idx] = 0.f;
        }
    }

    // F = x[src]
    for (int i = tid; i < EB*72; i += NTH){
        int e = i/72, dcol = i - e*72;
        float v = 0.f;
        if (e < e_act){ int s = ei[base + e]; v = x[s*72 + dcol]; }
        F[e*F_STR + dcol] = v;
    }
    __syncthreads();

    // prefetch W3 tile for instance 0 (LDGs overlap the MLP below)
    float wreg[25];
    w3_prefetch(W3, 0, tid, wreg);

    // ---- MLP: h0(B) -> h1(A) -> h2(B) -> h3(A) ----
    mlp_layer(B, A, Wsh, lane, ocol, 10);
    __syncthreads();
    for (int i = tid; i < 10000; i += NTH) Wsh[i] = W1[i]*0.1f;
    __syncthreads();
    mlp_layer(A, B, Wsh, lane, ocol, 100);
    __syncthreads();
    for (int i = tid; i < 10000; i += NTH) Wsh[i] = W2[i]*0.1f;
    __syncthreads();
    mlp_layer(B, A, Wsh, lane, ocol, 100);
    __syncthreads();

    // ---- phase B: 19 tensor-product instances, fused W3-GEMM + CG contraction ----
    for (int inst = 0; inst < 19; inst++){
        const int lo = c_lo[inst], li = c_li[inst], l = c_l[inst];
        const int P2 = 2*lo+1, Q2 = 2*li+1, Rd = 2*l+1;
        const int foff = c_foff[inst], cgo = c_cgoff[inst];
        const int sbase = (lo == 0) ? 0 : (lo == 1 ? 1 : 4);   // msg_acc slot base
        const float nrm = g_norm[lo];

        // dump prefetched W3 tile to smem: Wsh[i], i = tid + j*256 (= [k][c], k=i>>6, c=i&63)
        #pragma unroll
        for (int j=0;j<25;j++) Wsh[tid + j*NTH] = wreg[j];

        // per-edge T[v,p] = sum_q F[v,q] * (sum_r C[p,q,r]*Yl[r])
        // 2 threads per edge (p-parity split) -> 192 active threads.
        // F block hoisted to registers once per (edge, instance).
        {
            int e  = tid >> 1;
            int ph = tid & 1;
            if (e < e_act){
                float Yl[9];
                for (int r2=0;r2<Rd;r2++) Yl[r2] = Ysh[e*Y_STR + l*l + r2];
                float Fv[8][5];
                #pragma unroll
                for (int v=0;v<8;v++)
                    #pragma unroll
                    for (int q=0;q<5;q++)
                        Fv[v][q] = (q < Q2) ? F[e*F_STR + foff + v*Q2 + q] : 0.f;
                for (int p=ph;p<P2;p+=2){
                    float Gq[5];
                    #pragma unroll
                    for (int q=0;q<5;q++){
                        float s = 0.f;
                        if (q < Q2)
                            for (int r2=0;r2<Rd;r2++) s += CGs[cgo + (p*Q2 + q)*Rd + r2]*Yl[r2];
                        Gq[q] = s;
                    }
                    #pragma unroll
                    for (int v=0;v<8;v++){
                        float t = 0.f;
                        #pragma unroll
                        for (int q=0;q<5;q++) t += Fv[v][q]*Gq[q];
                        T[e*T_STR + v*P2 + p] = t;
                    }
                }
            }
        }

        // prefetch next instance's W3 tile (overlaps the GEMM below)
        if (inst + 1 < 19) w3_prefetch(W3, inst + 1, tid, wreg);

        __syncthreads();

        // GEMM 96x100x64 with packed f32x2: thread = 3 edges x 8 cols (u=ocol, col pairs)
        unsigned long long acc2[3][4];
        #pragma unroll
        for (int i=0;i<3;i++)
            #pragma unroll
            for (int j=0;j<4;j++) acc2[i][j] = 0ull;
        const float* wp = &Wsh[ocol*8];
        for (int k=0;k<100;k++){
            unsigned long long hh0 = pack2(A[ lane      *H_STR + k]);
            unsigned long long hh1 = pack2(A[(lane+32)  *H_STR + k]);
            unsigned long long hh2 = pack2(A[(lane+64)  *H_STR + k]);
            ulonglong2 wA = *(const ulonglong2*)&wp[k*64];      // cols 0-3
            ulonglong2 wB = *(const ulonglong2*)&wp[k*64 + 4];  // cols 4-7
            ffma2(acc2[0][0], hh0, wA.x); ffma2(acc2[0][1], hh0, wA.y);
            ffma2(acc2[0][2], hh0, wB.x); ffma2(acc2[0][3], hh0, wB.y);
            ffma2(acc2[1][0], hh1, wA.x); ffma2(acc2[1][1], hh1, wA.y);
            ffma2(acc2[1][2], hh1, wB.x); ffma2(acc2[1][3], hh1, wB.y);
            ffma2(acc2[2][0], hh2, wA.x); ffma2(acc2[2][1], hh2, wA.y);
            ffma2(acc2[2][2], hh2, wB.x); ffma2(acc2[2][3], hh2, wB.y);
        }

        // msg_acc[i][sbase+p] += nrm * sum_v R[u,v]*T[v,p]
        #pragma unroll
        for (int i=0;i<3;i++){
            int e = lane + 32*i;
            if (e < e_act){
                float accf[8];
                #pragma unroll
                for (int j=0;j<4;j++){
                    F2U cv; cv.u = acc2[i][j];
                    accf[2*j]   = cv.f.x;
                    accf[2*j+1] = cv.f.y;
                }
                for (int p=0;p<P2;p++){
                    float s = 0.f;
                    #pragma unroll
                    for (int v=0;v<8;v++) s += accf[v]*T[e*T_STR + v*P2 + p];
                    msg_acc[i][sbase + p] += nrm*s;
                }
            }
        }
        __syncthreads();
    }

    // ---- scatter-add to out[dst]: thread owns cols {u=ocol} of its 3 edges ----
    #pragma unroll
    for (int i=0;i<3;i++){
        int e = lane + 32*i;
        if (e < e_act){
            int ob = DST[e]*72;
            atomicAdd(&out[ob + ocol], msg_acc[i][0]);                       // rep0: col u
            #pragma unroll
            for (int p=0;p<3;p++)
                atomicAdd(&out[ob + 8 + ocol*3 + p], msg_acc[i][1 + p]);     // rep1
            #pragma unroll
            for (int p=0;p<5;p++)
                atomicAdd(&out[ob + 32 + ocol*5 + p], msg_acc[i][4 + p]);    // rep2
        }
    }
}

// ---------------- launch ----------------
extern "C" void kernel_launch(void* const* d_in, const int* in_sizes, int n_in,
                              void* d_out, int out_size)
{
    const int*   ei   = (const int*)  d_in[0];
    const float* x    = (const float*)d_in[1];
    const float* dist = (const float*)d_in[2];
    const float* rvec = (const float*)d_in[3];
    const float* W0   = (const float*)d_in[4];
    const float* W1   = (const float*)d_in[5];
    const float* W2   = (const float*)d_in[6];
    const float* W3   = (const float*)d_in[7];
    float* out = (float*)d_out;
    const int E = in_sizes[2];

    size_t smem = (size_t)(EB*H_STR*2 + WSH_PAD + EB*F_STR +
                           EB*Y_STR + EB*T_STR + 1232 + 128)*sizeof(float);
    cudaFuncSetAttribute(tfn_main, cudaFuncAttributeMaxDynamicSharedMemorySize, (int)smem);

    cg_init_kernel<<<8, 192>>>();
    zero_kernel<<<(out_size + 255)/256, 256>>>(out, out_size);
    int nb = (E + EB - 1)/EB;
    tfn_main<<<nb, NTH, smem>>>(ei, x, dist, rvec, W0, W1, W2, W3, out, E);
}

// round 10
// speedup vs baseline: 1.1176x; 1.1176x over previous
#include <cuda_runtime.h>

#define EB     96
#define NTH    256
#define H_STR  101
#define F_STR  73
#define Y_STR  26
#define T_STR  41
#define WSH_PAD 10112
#define DPI    3.14159265358979323846
#define CGB    154          // CG blocks in prep kernel (8 warps each -> 1232 warps >= 1225)
#define ZB     704          // zeroing blocks in prep kernel

// ---------------- device globals (scratch, no allocation) ----------------
__device__ float g_CG[1225];
__device__ float g_K[25];
__device__ float g_norm[3];

// 19 tensor-product instances: (lo, li, l) with kk = index of l within the pair
__constant__ int c_lo[19]   = {0,0,0,1,1,1,1,1,1,1,2,2,2,2,2,2,2,2,2};
__constant__ int c_li[19]   = {0,1,2,0,1,1,1,2,2,2,0,1,1,1,2,2,2,2,2};
__constant__ int c_l [19]   = {0,1,2,1,0,1,2,1,2,3,2,1,2,3,0,1,2,3,4};
__constant__ int c_kk[19]   = {0,0,0,0,0,1,2,0,1,2,0,0,1,2,0,1,2,3,4};
__constant__ int c_roff[19] = {0,64,128,192,256,256,256,448,448,448,640,704,704,704,896,896,896,896,896};
__constant__ int c_foff[19] = {0,8,32,0,8,8,8,32,32,32,0,8,8,8,32,32,32,32,32};
__constant__ int c_cgoff[19]= {0,1,10,35,44,53,80,125,170,245,350,375,420,495,600,625,700,825,1000};
__constant__ int c_nl[19]   = {1,1,1,1,3,3,3,3,3,3,1,3,3,3,5,5,5,5,5};

// ---------------- packed f32x2 helpers (Blackwell FFMA2) ----------------
union F2U { unsigned long long u; float2 f; };

__device__ __forceinline__ unsigned long long pack2(float a){
    unsigned long long r;
    asm("mov.b64 %0, {%1, %1};" : "=l"(r) : "r"(__float_as_uint(a)));
    return r;
}
__device__ __forceinline__ void ffma2(unsigned long long& d,
                                      unsigned long long a, unsigned long long b){
    asm("fma.rn.f32x2 %0, %1, %2, %0;" : "+l"(d) : "l"(a), "l"(b));
}

// ---------------- CG helpers ----------------
__device__ double dfact_s(int n){ double r=1.0; for(int i=2;i<=n;i++) r*=(double)i; return r; }

// w3j with precomputed factorial table (selection rules guaranteed by caller)
__device__ double w3j_t(const double* ft,int j1,int j2,int j3,int m1,int m2,int m3){
    double pre = sqrt( ft[j1+j2-j3]*ft[j1-j2+j3]*ft[-j1+j2+j3]/ft[j1+j2+j3+1]
                     * ft[j1+m1]*ft[j1-m1]*ft[j2+m2]*ft[j2-m2]
                     * ft[j3+m3]*ft[j3-m3] );
    int kmin = max(0, max(j2-j3-m1, j1-j3+m2));
    int kmax = min(j1+j2-j3, min(j1-m1, j2+m2));
    double s = 0.0;
    for (int k=kmin;k<=kmax;k++){
        double den = ft[k]*ft[j1+j2-j3-k]*ft[j1-m1-k]*ft[j2+m2-k]
                   * ft[j3-j2+m1+k]*ft[j3-j1-m2+k];
        s += ((k&1)?-1.0:1.0)/den;
    }
    int ex = j1-j2-m3;
    double sgn = (ex & 1) ? -1.0 : 1.0;
    return sgn*pre*s;
}

// complex->real SH change-of-basis: row a (0..2l), complex col index m (-l..l)
__device__ void u_c2r(int l, int a, int m, double& re, double& im){
    re = 0.0; im = 0.0;
    const double is2 = 0.70710678118654752440;
    if (a == l){ if (m == 0) re = 1.0; return; }
    if (a > l){
        int mm = a - l;
        if      (m ==  mm) re = ((mm&1)?-1.0:1.0)*is2;
        else if (m == -mm) re = is2;
    } else {
        int mm = l - a;
        if      (m == -mm) im = is2;
        else if (m ==  mm) im = -((mm&1)?-1.0:1.0)*is2;
    }
}

// ---------------- merged prep kernel: CG init (warp per element) + zero(out) ----------------
__global__ void prep_kernel(float* __restrict__ out, int out_size){
    if (blockIdx.x < CGB){
        // small tables (block 0 only; lanes re-converge before the shuffle below)
        if (blockIdx.x == 0 && threadIdx.x < 28){
            int idx = threadIdx.x;
            if (idx < 25){
                int l = 0; while ((l+1)*(l+1) <= idx) l++;
                int m = idx - l*l - l;
                int am = m < 0 ? -m : m;
                double K = sqrt((2.0*l+1.0)/(4.0*DPI) * dfact_s(l-am)/dfact_s(l+am));
                if (m != 0) K *= sqrt(2.0);
                g_K[idx] = (float)K;
            } else {
                int lo = idx - 25;
                int nse = (lo==0)?24:(lo==1?56:72);
                g_norm[lo] = (float)(sqrt(4.0*DPI)*sqrt(2.0*lo+1.0)/sqrt((double)nse));
            }
        }

        // one warp per CG element; lanes parallelize the (m1,m2) terms
        int e    = blockIdx.x*8 + (threadIdx.x >> 5);
        int lane = threadIdx.x & 31;
        if (e < 1225){
            double ft[10];
            ft[0] = 1.0;
            #pragma unroll
            for (int i=1;i<10;i++) ft[i] = ft[i-1]*(double)i;

            int inst = 0;
            for (int i2=1;i2<19;i2++) if (e >= c_cgoff[i2]) inst = i2;
            int lo = c_lo[inst], li = c_li[inst], l3 = c_l[inst];
            int n1 = 2*lo+1, n2 = 2*li+1, Rd = 2*l3+1;
            int off = e - c_cgoff[inst];
            int a = off/(n2*Rd);
            int rem = off - a*n2*Rd;
            int b = rem/Rd;
            int c = rem - b*Rd;

            double t = 0.0;
            if (lane < n1*n2){
                int m1 = lane/n2 - lo;
                int m2 = lane%n2 - li;
                int m3 = -(m1+m2);
                if (m3 >= -l3 && m3 <= l3){
                    double u1r,u1i,u2r,u2i,u3r,u3i;
                    u_c2r(lo,a,m1,u1r,u1i);
                    u_c2r(li,b,m2,u2r,u2i);
                    u_c2r(l3,c,m3,u3r,u3i);
                    bool nz1 = (u1r!=0.0)||(u1i!=0.0);
                    bool nz2 = (u2r!=0.0)||(u2i!=0.0);
                    bool nz3 = (u3r!=0.0)||(u3i!=0.0);
                    if (nz1 && nz2 && nz3){
                        double w = w3j_t(ft, lo,li,l3,m1,m2,m3);
                        double p12r = u1r*u2r - u1i*u2i;
                        double p12i = u1r*u2i + u1i*u2r;
                        double pr = p12r*u3r - p12i*u3i;
                        double pi = p12r*u3i + p12i*u3r;
                        t = (pr + pi)*w;
                    }
                }
            }
            // warp-sum (all 32 lanes converged here)
            #pragma unroll
            for (int o=16;o>0;o>>=1) t += __shfl_down_sync(0xffffffffu, t, o);
            if (lane == 0) g_CG[e] = (float)t;
        }
    } else {
        // zero the output buffer (float4, grid-stride)
        float4 z = make_float4(0.f,0.f,0.f,0.f);
        int n4 = out_size >> 2;
        int stride = (gridDim.x - CGB)*blockDim.x;
        for (int i4 = (blockIdx.x - CGB)*blockDim.x + threadIdx.x; i4 < n4; i4 += stride)
            reinterpret_cast<float4*>(out)[i4] = z;
        if (blockIdx.x == CGB && threadIdx.x < (out_size & 3))
            out[(n4<<2) + threadIdx.x] = 0.f;
    }
}

// ---------------- MLP layer with f32x2: dst[e][o] = silu(sum_k src[e][k]*Wsh[k][o]) ----
__device__ __forceinline__ void mlp_layer(const float* __restrict__ src, float* __restrict__ dst,
                                          const float* __restrict__ Wsh, int lane, int ocol, int K){
    unsigned long long acc[3][7];
    #pragma unroll
    for (int i=0;i<3;i++)
        #pragma unroll
        for (int j=0;j<7;j++) acc[i][j] = 0ull;
    const int cb = ocol*2;
    for (int k=0;k<K;k++){
        unsigned long long hh0 = pack2(src[ lane      *H_STR + k]);
        unsigned long long hh1 = pack2(src[(lane+32)  *H_STR + k]);
        unsigned long long hh2 = pack2(src[(lane+64)  *H_STR + k]);
        #pragma unroll
        for (int j=0;j<7;j++){
            unsigned long long w = *(const unsigned long long*)&Wsh[k*100 + cb + 16*j];
            ffma2(acc[0][j], hh0, w);
            ffma2(acc[1][j], hh1, w);
            ffma2(acc[2][j], hh2, w);
        }
    }
    #pragma unroll
    for (int i=0;i<3;i++)
        #pragma unroll
        for (int j=0;j<7;j++){
            int c = cb + 16*j;
            F2U cv; cv.u = acc[i][j];
            if (c < 100){
                float v = cv.f.x;
                dst[(lane + 32*i)*H_STR + c] = v / (1.f + __expf(-v));
            }
            if (c + 1 < 100){
                float v = cv.f.y;
                dst[(lane + 32*i)*H_STR + c + 1] = v / (1.f + __expf(-v));
            }
        }
}

// prefetch next W3 tile into registers (25 per thread)
__device__ __forceinline__ void w3_prefetch(const float* __restrict__ W3, int inst,
                                            int tid, float* wreg){
    const int roff = c_roff[inst], nl = c_nl[inst], kk = c_kk[inst];
    #pragma unroll
    for (int j=0;j<25;j++){
        int i = tid + j*NTH;
        int k = i >> 6, c = i & 63;
        wreg[j] = W3[k*1216 + roff + c*nl + kk] * 0.1f;
    }
}

// ---------------- main fused kernel ----------------
__global__ void __launch_bounds__(NTH, 1)
tfn_main(const int* __restrict__ ei, const float* __restrict__ x,
         const float* __restrict__ dist, const float* __restrict__ rvec,
         const float* __restrict__ W0, const float* __restrict__ W1,
         const float* __restrict__ W2, const float* __restrict__ W3,
         float* __restrict__ out, int E)
{
    extern __shared__ float sm[];
    float* A   = sm;                    // [96][101]  h1 / h3
    float* B   = A   + EB*H_STR;        // [96][101]  h0 / h2
    float* Wsh = B   + EB*H_STR;        // WSH_PAD floats: W0/W1/W2 staged; then W3 tile [100][64]
    float* F   = Wsh + WSH_PAD;         // [96][73]
    float* Ysh = F   + EB*F_STR;        // [96][26]
    float* T   = Ysh + EB*Y_STR;        // [96][41]
    float* CGs = T   + EB*T_STR;        // 1225 (padded 1232)
    int*  DST  = (int*)(CGs + 1232);    // [96]

    const int tid  = threadIdx.x;
    const int lane = tid & 31;
    const int ocol = tid >> 5;          // 0..7
    const int base = blockIdx.x * EB;
    const int e_act = min(EB, E - base);

    // per-thread message accumulators: 3 edges x 9 cols (rep0:1, rep1:3, rep2:5) for u=ocol
    float msg_acc[3][9];
    #pragma unroll
    for (int i=0;i<3;i++)
        #pragma unroll
        for (int s=0;s<9;s++) msg_acc[i][s] = 0.f;

    // ---- stage S0: W0 (+zero pad), CG, basis -> B, spherical harmonics, F gather ----
    for (int i = tid; i < 1000; i += NTH) Wsh[i] = W0[i] * 0.31622776601683794f; // /sqrt(10)
    for (int i = 10000 + tid; i < WSH_PAD; i += NTH) Wsh[i] = 0.f;               // pad (read-only lanes)
    for (int i = tid; i < 1225; i += NTH) CGs[i] = g_CG[i];

    if (tid < EB){
        int e = tid;
        bool act = (e < e_act);
        DST[e] = act ? ei[E + base + e] : 0;

        // gaussian basis
        float d = act ? dist[base + e] : 0.f;
        #pragma unroll
        for (int k=0;k<10;k++){
            float c = 0.7f + (2.5f/9.f)*(float)k;
            float t = (d - c) * 4.5f;                       // 1/sigma = 9/(0.8*2.5)
            B[e*H_STR + k] = act ? __expf(-t*t) * (1.f/1.423085244900308f) : 0.f;
        }

        // spherical harmonics (lmax=4), matching reference recurrences
        float vx=0.f, vy=0.f, vz=0.f;
        if (act){ vx = rvec[(base+e)*3]; vy = rvec[(base+e)*3+1]; vz = rvec[(base+e)*3+2]; }
        float r   = sqrtf(vx*vx + vy*vy + vz*vz);
        float inv = 1.f / fmaxf(r, 1e-9f);
        float X = vx*inv, Yc = vy*inv, Z = vz*inv;
        float Am[5], Bm[5];
        Am[0] = 1.f; Bm[0] = 0.f;
        #pragma unroll
        for (int m=1;m<=4;m++){
            Am[m] = X*Am[m-1] - Yc*Bm[m-1];
            Bm[m] = X*Bm[m-1] + Yc*Am[m-1];
        }
        float P[5][5];
        P[0][0] = 1.f;
        #pragma unroll
        for (int m=0;m<=4;m++){
            if (m > 0) P[m][m] = -(2.f*m - 1.f)*P[m-1][m-1];
            if (m < 4) P[m+1][m] = (2.f*m + 1.f)*Z*P[m][m];
            #pragma unroll
            for (int l=m+2;l<=4;l++)
                P[l][m] = ((2.f*l - 1.f)*Z*P[l-1][m] - (l + m - 1.f)*P[l-2][m]) / (float)(l - m);
        }
        if (act){
            int idx = 0;
            #pragma unroll
            for (int l=0;l<=4;l++){
                #pragma unroll
                for (int m=-l;m<=l;m++,idx++){
                    int am = (m < 0) ? -m : m;
                    float K = g_K[idx];
                    float val = (m == 0) ? K*P[l][0]
                              : (m > 0)  ? K*P[l][m]*Am[m]
                                         : K*P[l][am]*Bm[am];
                    Ysh[e*Y_STR + idx] = val;
                }
            }
        } else {
            for (int idx=0; idx<25; idx++) Ysh[e*Y_STR + idx] = 0.f;
        }
    }

    // F = x[src]
    for (int i = tid; i < EB*72; i += NTH){
        int e = i/72, dcol = i - e*72;
        float v = 0.f;
        if (e < e_act){ int s = ei[base + e]; v = x[s*72 + dcol]; }
        F[e*F_STR + dcol] = v;
    }
    __syncthreads();

    // prefetch W3 tile for instance 0 (LDGs overlap the MLP below)
    float wreg[25];
    w3_prefetch(W3, 0, tid, wreg);

    // ---- MLP: h0(B) -> h1(A) -> h2(B) -> h3(A) ----
    mlp_layer(B, A, Wsh, lane, ocol, 10);
    __syncthreads();
    for (int i = tid; i < 10000; i += NTH) Wsh[i] = W1[i]*0.1f;
    __syncthreads();
    mlp_layer(A, B, Wsh, lane, ocol, 100);
    __syncthreads();
    for (int i = tid; i < 10000; i += NTH) Wsh[i] = W2[i]*0.1f;
    __syncthreads();
    mlp_layer(B, A, Wsh, lane, ocol, 100);
    __syncthreads();

    // ---- phase B: 19 tensor-product instances, fused W3-GEMM + CG contraction ----
    for (int inst = 0; inst < 19; inst++){
        const int lo = c_lo[inst], li = c_li[inst], l = c_l[inst];
        const int P2 = 2*lo+1, Q2 = 2*li+1, Rd = 2*l+1;
        const int foff = c_foff[inst], cgo = c_cgoff[inst];
        const int sbase = (lo == 0) ? 0 : (lo == 1 ? 1 : 4);   // msg_acc slot base
        const float nrm = g_norm[lo];

        // dump prefetched W3 tile to smem: Wsh[i], i = tid + j*256 (= [k][c], k=i>>6, c=i&63)
        #pragma unroll
        for (int j=0;j<25;j++) Wsh[tid + j*NTH] = wreg[j];

        // per-edge T[v,p] = sum_q F[v,q] * (sum_r C[p,q,r]*Yl[r])
        // 2 threads per edge (p-parity split) -> 192 active threads.
        {
            int e  = tid >> 1;
            int ph = tid & 1;
            if (e < e_act){
                float Yl[9];
                for (int r2=0;r2<Rd;r2++) Yl[r2] = Ysh[e*Y_STR + l*l + r2];
                float Fv[8][5];
                #pragma unroll
                for (int v=0;v<8;v++)
                    #pragma unroll
                    for (int q=0;q<5;q++)
                        Fv[v][q] = (q < Q2) ? F[e*F_STR + foff + v*Q2 + q] : 0.f;
                for (int p=ph;p<P2;p+=2){
                    float Gq[5];
                    #pragma unroll
                    for (int q=0;q<5;q++){
                        float s = 0.f;
                        if (q < Q2)
                            for (int r2=0;r2<Rd;r2++) s += CGs[cgo + (p*Q2 + q)*Rd + r2]*Yl[r2];
                        Gq[q] = s;
                    }
                    #pragma unroll
                    for (int v=0;v<8;v++){
                        float t = 0.f;
                        #pragma unroll
                        for (int q=0;q<5;q++) t += Fv[v][q]*Gq[q];
                        T[e*T_STR + v*P2 + p] = t;
                    }
                }
            }
        }

        // prefetch next instance's W3 tile (overlaps the GEMM below)
        if (inst + 1 < 19) w3_prefetch(W3, inst + 1, tid, wreg);

        __syncthreads();

        // GEMM 96x100x64 with packed f32x2: thread = 3 edges x 8 cols (u=ocol, col pairs)
        unsigned long long acc2[3][4];
        #pragma unroll
        for (int i=0;i<3;i++)
            #pragma unroll
            for (int j=0;j<4;j++) acc2[i][j] = 0ull;
        const float* wp = &Wsh[ocol*8];
        for (int k=0;k<100;k++){
            unsigned long long hh0 = pack2(A[ lane      *H_STR + k]);
            unsigned long long hh1 = pack2(A[(lane+32)  *H_STR + k]);
            unsigned long long hh2 = pack2(A[(lane+64)  *H_STR + k]);
            ulonglong2 wA = *(const ulonglong2*)&wp[k*64];      // cols 0-3
            ulonglong2 wB = *(const ulonglong2*)&wp[k*64 + 4];  // cols 4-7
            ffma2(acc2[0][0], hh0, wA.x); ffma2(acc2[0][1], hh0, wA.y);
            ffma2(acc2[0][2], hh0, wB.x); ffma2(acc2[0][3], hh0, wB.y);
            ffma2(acc2[1][0], hh1, wA.x); ffma2(acc2[1][1], hh1, wA.y);
            ffma2(acc2[1][2], hh1, wB.x); ffma2(acc2[1][3], hh1, wB.y);
            ffma2(acc2[2][0], hh2, wA.x); ffma2(acc2[2][1], hh2, wA.y);
            ffma2(acc2[2][2], hh2, wB.x); ffma2(acc2[2][3], hh2, wB.y);
        }

        // msg_acc[i][sbase+p] += nrm * sum_v R[u,v]*T[v,p]
        #pragma unroll
        for (int i=0;i<3;i++){
            int e = lane + 32*i;
            if (e < e_act){
                float accf[8];
                #pragma unroll
                for (int j=0;j<4;j++){
                    F2U cv; cv.u = acc2[i][j];
                    accf[2*j]   = cv.f.x;
                    accf[2*j+1] = cv.f.y;
                }
                for (int p=0;p<P2;p++){
                    float s = 0.f;
                    #pragma unroll
                    for (int v=0;v<8;v++) s += accf[v]*T[e*T_STR + v*P2 + p];
                    msg_acc[i][sbase + p] += nrm*s;
                }
            }
        }
        __syncthreads();
    }

    // ---- scatter-add to out[dst]: thread owns cols {u=ocol} of its 3 edges ----
    #pragma unroll
    for (int i=0;i<3;i++){
        int e = lane + 32*i;
        if (e < e_act){
            int ob = DST[e]*72;
            atomicAdd(&out[ob + ocol], msg_acc[i][0]);                       // rep0: col u
            #pragma unroll
            for (int p=0;p<3;p++)
                atomicAdd(&out[ob + 8 + ocol*3 + p], msg_acc[i][1 + p]);     // rep1
            #pragma unroll
            for (int p=0;p<5;p++)
                atomicAdd(&out[ob + 32 + ocol*5 + p], msg_acc[i][4 + p]);    // rep2
        }
    }
}

// ---------------- launch ----------------
extern "C" void kernel_launch(void* const* d_in, const int* in_sizes, int n_in,
                              void* d_out, int out_size)
{
    const int*   ei   = (const int*)  d_in[0];
    const float* x    = (const float*)d_in[1];
    const float* dist = (const float*)d_in[2];
    const float* rvec = (const float*)d_in[3];
    const float* W0   = (const float*)d_in[4];
    const float* W1   = (const float*)d_in[5];
    const float* W2   = (const float*)d_in[6];
    const float* W3   = (const float*)d_in[7];
    float* out = (float*)d_out;
    const int E = in_sizes[2];

    size_t smem = (size_t)(EB*H_STR*2 + WSH_PAD + EB*F_STR +
                           EB*Y_STR + EB*T_STR + 1232 + 128)*sizeof(float);
    cudaFuncSetAttribute(tfn_main, cudaFuncAttributeMaxDynamicSharedMemorySize, (int)smem);

    prep_kernel<<<CGB + ZB, NTH>>>(out, out_size);
    int nb = (E + EB - 1)/EB;
    tfn_main<<<nb, NTH, smem>>>(ei, x, dist, rvec, W0, W1, W2, W3, out, E);
}